// round 13
// baseline (speedup 1.0000x reference)
#include <cuda_runtime.h>
#include <cuda_bf16.h>
#include <stdint.h>

#define NTOK 65536
#define F 256

typedef __nv_bfloat16 bf16;
typedef __nv_bfloat162 bf162;

// ---------------- scratch ----------------
__device__ __align__(128) uint8_t g_XM8[(size_t)NTOK * F];       // fp8 LN1-mod output
__device__ __align__(128) uint8_t g_QK8[(size_t)NTOK * 512];     // fp8 Q|K per token
__device__ __align__(128) bf16 g_V[(size_t)NTOK * F];            // bf16 V
__device__ __align__(128) uint8_t g_AO8[(size_t)NTOK * F];       // fp8 attention output
__device__ __align__(128) float g_Ae[256 * F];
__device__ __align__(128) float g_Be[256 * F];
__device__ __align__(128) uint8_t g_W8qkv[768 * F];              // [n][k] e4m3
__device__ __align__(128) uint8_t g_W8o[F * F];
__device__ __align__(128) uint8_t g_W8_1[F * F];
__device__ __align__(128) uint8_t g_W8_2[F * F];
__device__ __align__(128) float g_bqkv[3 * F];
// Schraudolph-folded bias: valid -> 1064986823.0 ; masked -> 142239943.0
__device__ __align__(128) float g_bias[NTOK];

// ---------------- helpers ----------------
__device__ __forceinline__ uint32_t smaddr(const void* p) {
    return (uint32_t)__cvta_generic_to_shared(p);
}
__device__ __forceinline__ void cpasync16(uint32_t dst, const void* src) {
    asm volatile("cp.async.cg.shared.global [%0], [%1], 16;\n" :: "r"(dst), "l"(src));
}
__device__ __forceinline__ void cpcommit() {
    asm volatile("cp.async.commit_group;\n");
}
__device__ __forceinline__ void ldm2(uint32_t* r, const void* p) {
    asm volatile("ldmatrix.sync.aligned.m8n8.x2.shared.b16 {%0,%1}, [%2];\n"
                 : "=r"(r[0]), "=r"(r[1]) : "r"(smaddr(p)));
}
__device__ __forceinline__ void ldm4(uint32_t* r, const void* p) {
    asm volatile("ldmatrix.sync.aligned.m8n8.x4.shared.b16 {%0,%1,%2,%3}, [%4];\n"
                 : "=r"(r[0]), "=r"(r[1]), "=r"(r[2]), "=r"(r[3]) : "r"(smaddr(p)));
}
__device__ __forceinline__ void ldm4t(uint32_t* r, const void* p) {
    asm volatile("ldmatrix.sync.aligned.m8n8.x4.trans.shared.b16 {%0,%1,%2,%3}, [%4];\n"
                 : "=r"(r[0]), "=r"(r[1]), "=r"(r[2]), "=r"(r[3]) : "r"(smaddr(p)));
}
__device__ __forceinline__ void mma16816(float* d, const uint32_t* a, const uint32_t* b) {
    asm volatile("mma.sync.aligned.m16n8k16.row.col.f32.bf16.bf16.f32 "
                 "{%0,%1,%2,%3}, {%4,%5,%6,%7}, {%8,%9}, {%0,%1,%2,%3};\n"
                 : "+f"(d[0]), "+f"(d[1]), "+f"(d[2]), "+f"(d[3])
                 : "r"(a[0]), "r"(a[1]), "r"(a[2]), "r"(a[3]), "r"(b[0]), "r"(b[1]));
}
__device__ __forceinline__ void mma16832(float* d, const uint32_t* a, uint32_t b0, uint32_t b1) {
    asm volatile("mma.sync.aligned.m16n8k32.row.col.f32.e4m3.e4m3.f32 "
                 "{%0,%1,%2,%3}, {%4,%5,%6,%7}, {%8,%9}, {%0,%1,%2,%3};\n"
                 : "+f"(d[0]), "+f"(d[1]), "+f"(d[2]), "+f"(d[3])
                 : "r"(a[0]), "r"(a[1]), "r"(a[2]), "r"(a[3]), "r"(b0), "r"(b1));
}
__device__ __forceinline__ uint32_t packbf(float a, float b) {
    bf162 h = __floats2bfloat162_rn(a, b);
    return *reinterpret_cast<uint32_t*>(&h);
}
__device__ __forceinline__ uint16_t pack2_e4m3(float lo, float hi) {
    uint16_t r;
    asm("cvt.rn.satfinite.e4m3x2.f32 %0, %1, %2;" : "=h"(r) : "f"(hi), "f"(lo));
    return r;
}
__device__ __forceinline__ uint32_t pack4_e4m3(float v0, float v1, float v2, float v3) {
    uint16_t lo = pack2_e4m3(v0, v1);
    uint16_t hi = pack2_e4m3(v2, v3);
    return (uint32_t)lo | ((uint32_t)hi << 16);
}
__device__ __forceinline__ uint8_t to_e4m3(float a) {
    return (uint8_t)pack2_e4m3(a, 0.f);
}

// ---------------- fused prep ----------------
__global__ void k_prep(const float* __restrict__ pos, const float* __restrict__ Wemb,
                       const float* __restrict__ bemb, const float* __restrict__ g1,
                       const float* __restrict__ b1,
                       const float* __restrict__ Wq, const float* __restrict__ Wk,
                       const float* __restrict__ Wv, const float* __restrict__ bq,
                       const float* __restrict__ bk, const float* __restrict__ bv,
                       const float* __restrict__ Wo, const float* __restrict__ W1,
                       const float* __restrict__ W2,
                       const void* __restrict__ mask, float* __restrict__ outmask,
                       int write_out) {
    int blk = blockIdx.x;
    int tid = threadIdx.x;
    if (blk < 256) {
        __shared__ float p[F];
        int t = blk, c = tid;
        p[c] = pos[t * F + c];
        __syncthreads();
        float sh = bemb[c], sc = bemb[F + c];
#pragma unroll 4
        for (int k = 0; k < F; k++) {
            float pv = p[k];
            sh = fmaf(pv, Wemb[k * 512 + c], sh);
            sc = fmaf(pv, Wemb[k * 512 + 256 + c], sc);
        }
        g_Ae[t * F + c] = g1[c] * (1.f + sc);
        g_Be[t * F + c] = b1[c] * (1.f + sc) + sh;
    } else if (blk < 512) {
        int i = (blk - 256) * 256 + tid;
        int k = i >> 8, n = i & 255;
        g_W8qkv[(size_t)n * 256 + k]         = to_e4m3(Wq[i]);
        g_W8qkv[(size_t)(256 + n) * 256 + k] = to_e4m3(Wk[i]);
        g_W8qkv[(size_t)(512 + n) * 256 + k] = to_e4m3(Wv[i]);
        g_W8o[(size_t)n * 256 + k]  = to_e4m3(Wo[i]);
        g_W8_1[(size_t)n * 256 + k] = to_e4m3(W1[i]);
        g_W8_2[(size_t)n * 256 + k] = to_e4m3(W2[i]);
        if (i < F) {
            g_bqkv[i]         = bq[i];
            g_bqkv[F + i]     = bk[i];
            g_bqkv[2 * F + i] = bv[i];
        }
    } else {
        __shared__ int sAll[8];
        int w = blk - 512;
        uint32_t w0 = *(const uint32_t*)mask;
        int mode = (w0 == 0x01010101u) ? 0 : ((w0 == 0x3F800000u) ? 1 : 2);
        int idx = w * 256 + tid;
        int mv;
        if (mode == 0)      mv = (((const unsigned char*)mask)[idx] != 0);
        else if (mode == 1) mv = (((const float*)mask)[idx] != 0.f);
        else                mv = (((const int*)mask)[idx] != 0);
        g_bias[idx] = mv ? 1064986823.0f : 142239943.0f;
        unsigned bal = __ballot_sync(0xffffffffu, mv);
        if ((tid & 31) == 0) sAll[tid >> 5] = (bal == 0xffffffffu);
        __syncthreads();
        if (write_out) {
            int allv = sAll[0] & sAll[1] & sAll[2] & sAll[3] & sAll[4] & sAll[5] & sAll[6] & sAll[7];
            outmask[idx] = (mv && allv) ? 1.f : 0.f;
        }
    }
}

// ---------------- layernorm (LN1 + modulation) -> fp8 ----------------
__global__ void k_ln(const float* __restrict__ xin) {
    int warp = threadIdx.x >> 5, lane = threadIdx.x & 31;
    int tok = blockIdx.x * 8 + warp;
    const float4* row = (const float4*)(xin + (size_t)tok * F);
    float4 v0 = row[lane], v1 = row[lane + 32];
    float s  = v0.x + v0.y + v0.z + v0.w + v1.x + v1.y + v1.z + v1.w;
    float ss = v0.x * v0.x + v0.y * v0.y + v0.z * v0.z + v0.w * v0.w +
               v1.x * v1.x + v1.y * v1.y + v1.z * v1.z + v1.w * v1.w;
#pragma unroll
    for (int o = 16; o > 0; o >>= 1) {
        s  += __shfl_xor_sync(0xffffffffu, s, o);
        ss += __shfl_xor_sync(0xffffffffu, ss, o);
    }
    float mean = s * (1.f / 256.f);
    float var  = ss * (1.f / 256.f) - mean * mean;
    float r = rsqrtf(var + 1e-5f);
    const float4* a4 = (const float4*)(g_Ae + (size_t)(tok & 255) * F);
    const float4* b4 = (const float4*)(g_Be + (size_t)(tok & 255) * F);
    float4 a0 = a4[lane], a1 = a4[lane + 32];
    float4 b0 = b4[lane], b1 = b4[lane + 32];
    uint32_t* out = (uint32_t*)(g_XM8 + (size_t)tok * F);
    out[lane] = pack4_e4m3((v0.x - mean) * r * a0.x + b0.x,
                           (v0.y - mean) * r * a0.y + b0.y,
                           (v0.z - mean) * r * a0.z + b0.z,
                           (v0.w - mean) * r * a0.w + b0.w);
    out[lane + 32] = pack4_e4m3((v1.x - mean) * r * a1.x + b1.x,
                                (v1.y - mean) * r * a1.y + b1.y,
                                (v1.z - mean) * r * a1.z + b1.z,
                                (v1.w - mean) * r * a1.w + b1.w);
}

// ---------------- fp8 GEMM (QKV only): C = XM8 @ Wqkv^T -> Q,K fp8 / V bf16 ----------------
#define SMEM_G8 61440

__global__ void __launch_bounds__(256, 2) k_gemm0() {
    extern __shared__ char dsm[];
    uint8_t* sA = (uint8_t*)dsm;
    uint8_t* sB = (uint8_t*)(dsm + 30720);

    int tid = threadIdx.x;
    int lane = tid & 31, warp = tid >> 5;
    int wm = warp & 1, wn = warp >> 1;
    int bm = blockIdx.y * 128, bn = blockIdx.x * 128;

    float acc[4][4][4];
#pragma unroll
    for (int i = 0; i < 4; i++)
#pragma unroll
        for (int j = 0; j < 4; j++)
#pragma unroll
            for (int q = 0; q < 4; q++) acc[i][j][q] = 0.f;

    int lrow = tid >> 1, lseg = (tid & 1) * 32;
    const uint8_t* asrc0 = g_XM8 + (size_t)(bm + lrow) * 256 + lseg;
    const uint8_t* bsrc0 = g_W8qkv + (size_t)(bn + lrow) * 256 + lseg;
    uint32_t ad0 = smaddr(sA + (size_t)lrow * 80 + lseg);
    uint32_t bd0 = smaddr(sB + (size_t)lrow * 80 + lseg);

#define PREFETCH(st, k0)                                        \
    do {                                                        \
        uint32_t ad = ad0 + (st) * 10240;                       \
        cpasync16(ad, asrc0 + (k0));                            \
        cpasync16(ad + 16, asrc0 + (k0) + 16);                  \
        uint32_t bd = bd0 + (st) * 10240;                       \
        cpasync16(bd, bsrc0 + (k0));                            \
        cpasync16(bd + 16, bsrc0 + (k0) + 16);                  \
        cpcommit();                                             \
    } while (0)

    PREFETCH(0, 0);
    PREFETCH(1, 64);
#pragma unroll
    for (int ks = 0; ks < 4; ks++) {
        if (ks < 3) asm volatile("cp.async.wait_group 1;\n");
        else        asm volatile("cp.async.wait_group 0;\n");
        __syncthreads();
        if (ks < 2) PREFETCH((ks + 2) % 3, (ks + 2) * 64);
        int st = ks % 3;
        const uint8_t* sAs = sA + st * 10240;
        const uint8_t* sBs = sB + st * 10240;
#pragma unroll
        for (int kk2 = 0; kk2 < 2; kk2++) {
            uint32_t af[4][4];
#pragma unroll
            for (int mt = 0; mt < 4; mt++)
                ldm4(af[mt], sAs + (size_t)(wm * 64 + mt * 16 + (lane & 15)) * 80 +
                             kk2 * 32 + ((lane >> 4) & 1) * 16);
            uint32_t bfr[2][4];
#pragma unroll
            for (int nb = 0; nb < 2; nb++)
                ldm4(bfr[nb], sBs + (size_t)(wn * 32 + nb * 16 + (lane & 15)) * 80 +
                              kk2 * 32 + ((lane >> 4) & 1) * 16);
#pragma unroll
            for (int mt = 0; mt < 4; mt++)
#pragma unroll
                for (int nt = 0; nt < 4; nt++)
                    mma16832(acc[mt][nt], af[mt],
                             bfr[nt >> 1][nt & 1], bfr[nt >> 1][(nt & 1) + 2]);
        }
    }
#undef PREFETCH

#pragma unroll
    for (int mt = 0; mt < 4; mt++) {
        int r0 = bm + wm * 64 + mt * 16 + (lane >> 2);
#pragma unroll
        for (int nt = 0; nt < 4; nt++) {
            int cb = bn + wn * 32 + nt * 8 + (lane & 3) * 2;
            float b0 = g_bqkv[cb], b1 = g_bqkv[cb + 1];
            float c0 = acc[mt][nt][0] + b0, c1 = acc[mt][nt][1] + b1;
            float c2 = acc[mt][nt][2] + b0, c3 = acc[mt][nt][3] + b1;
            if (cb < 512) {
                *(uint16_t*)&g_QK8[(size_t)r0 * 512 + cb]       = pack2_e4m3(c0, c1);
                *(uint16_t*)&g_QK8[(size_t)(r0 + 8) * 512 + cb] = pack2_e4m3(c2, c3);
            } else {
                int vc = cb - 512;
                *(bf162*)&g_V[(size_t)r0 * 256 + vc]       = __floats2bfloat162_rn(c0, c1);
                *(bf162*)&g_V[(size_t)(r0 + 8) * 256 + vc] = __floats2bfloat162_rn(c2, c3);
            }
        }
    }
}

// ---------------- attention: fp8 QK (m16n8k32), bf16 PV, Schraudolph softmax ----------------
__global__ void __launch_bounds__(256, 2) k_attn() {
    __shared__ uint8_t smK8[256][48];
    __shared__ bf16 smV[256][40];
    __shared__ float sB2[256];
    int w = blockIdx.x, h = blockIdx.y;
    int tid = threadIdx.x, warp = tid >> 5, lane = tid & 31;
    const uint8_t* kbase = g_QK8 + (size_t)(w * 256) * 512 + 256 + h * 32;
    const bf16* vbase = g_V + (size_t)(w * 256) * 256 + h * 32;

    {
        const uint4* ks = (const uint4*)(kbase + (size_t)tid * 512);
        uint4 k0 = ks[0], k1 = ks[1];
        const uint4* vs = (const uint4*)(vbase + (size_t)tid * 256);
        uint4 v0 = vs[0], v1 = vs[1], v2 = vs[2], v3 = vs[3];
        *(uint4*)&smK8[tid][0] = k0;
        *(uint4*)&smK8[tid][16] = k1;
        uint4* vd = (uint4*)&smV[tid][0];
        vd[0] = v0; vd[1] = v1; vd[2] = v2; vd[3] = v3;
        sB2[tid] = g_bias[w * 256 + tid];
    }

    // fp8 Q fragments (A-operand m16n8k32, k=32 = full head dim)
    const uint8_t* qbase = g_QK8 + (size_t)(w * 256) * 512 + h * 32;
    int qr = lane >> 2, qc = (lane & 3) * 2, qc4 = (lane & 3) * 4;
    uint32_t qf[2][4];
#pragma unroll
    for (int mt = 0; mt < 2; mt++) {
        const uint8_t* qp = qbase + (size_t)(warp * 32 + mt * 16) * 512;
        qf[mt][0] = *(const uint32_t*)(qp + (size_t)qr * 512 + qc4);
        qf[mt][1] = *(const uint32_t*)(qp + (size_t)(qr + 8) * 512 + qc4);
        qf[mt][2] = *(const uint32_t*)(qp + (size_t)qr * 512 + 16 + qc4);
        qf[mt][3] = *(const uint32_t*)(qp + (size_t)(qr + 8) * 512 + 16 + qc4);
    }
    __syncthreads();

    float O[2][4][4];
    float Osum[2][4];
#pragma unroll
    for (int mt = 0; mt < 2; mt++) {
#pragma unroll
        for (int q = 0; q < 4; q++) Osum[mt][q] = 0.f;
#pragma unroll
        for (int d = 0; d < 4; d++)
#pragma unroll
            for (int q = 0; q < 4; q++) O[mt][d][q] = 0.f;
    }
    const float K1 = 0.17677669529663687f * 1.4426950408889634f * 8388608.f;
    uint32_t onesb[2] = {0x3F803F80u, 0x3F803F80u};

#pragma unroll
    for (int c = 0; c < 8; c++) {
        uint32_t pa[2][4][2];
#pragma unroll
        for (int nt = 0; nt < 4; nt++) {
            int key0 = c * 32 + nt * 8;
            uint32_t kb[2];
            ldm2(kb, &smK8[key0 + (lane & 7)][((lane >> 3) & 1) * 16]);
            float s0[4] = {0.f, 0.f, 0.f, 0.f};
            float s1[4] = {0.f, 0.f, 0.f, 0.f};
            mma16832(s0, qf[0], kb[0], kb[1]);
            mma16832(s1, qf[1], kb[0], kb[1]);
            int kcol = key0 + qc;
            float b0 = sB2[kcol], b1 = sB2[kcol + 1];
            float p00 = __int_as_float((int)fmaf(s0[0], K1, b0));
            float p01 = __int_as_float((int)fmaf(s0[1], K1, b1));
            float p02 = __int_as_float((int)fmaf(s0[2], K1, b0));
            float p03 = __int_as_float((int)fmaf(s0[3], K1, b1));
            float p10 = __int_as_float((int)fmaf(s1[0], K1, b0));
            float p11 = __int_as_float((int)fmaf(s1[1], K1, b1));
            float p12 = __int_as_float((int)fmaf(s1[2], K1, b0));
            float p13 = __int_as_float((int)fmaf(s1[3], K1, b1));
            pa[0][nt][0] = packbf(p00, p01);
            pa[0][nt][1] = packbf(p02, p03);
            pa[1][nt][0] = packbf(p10, p11);
            pa[1][nt][1] = packbf(p12, p13);
        }
#pragma unroll
        for (int kt2 = 0; kt2 < 2; kt2++) {
            uint32_t af0[4] = {pa[0][2 * kt2][0], pa[0][2 * kt2][1],
                               pa[0][2 * kt2 + 1][0], pa[0][2 * kt2 + 1][1]};
            uint32_t af1[4] = {pa[1][2 * kt2][0], pa[1][2 * kt2][1],
                               pa[1][2 * kt2 + 1][0], pa[1][2 * kt2 + 1][1]};
            mma16816(Osum[0], af0, onesb);
            mma16816(Osum[1], af1, onesb);
#pragma unroll
            for (int d2 = 0; d2 < 2; d2++) {
                uint32_t vb4[4];
                ldm4t(vb4, &smV[c * 32 + kt2 * 16 + (lane & 15)][d2 * 16 + ((lane >> 4) & 1) * 8]);
                mma16816(O[0][2 * d2],     af0, vb4);
                mma16816(O[0][2 * d2 + 1], af0, vb4 + 2);
                mma16816(O[1][2 * d2],     af1, vb4);
                mma16816(O[1][2 * d2 + 1], af1, vb4 + 2);
            }
        }
    }

#pragma unroll
    for (int mt = 0; mt < 2; mt++) {
        float il0 = 1.f / Osum[mt][0];
        float il1 = 1.f / Osum[mt][2];
        int r0 = w * 256 + warp * 32 + mt * 16 + qr;
#pragma unroll
        for (int d = 0; d < 4; d++) {
            int col = h * 32 + d * 8 + qc;
            *(uint16_t*)&g_AO8[(size_t)r0 * 256 + col] =
                pack2_e4m3(O[mt][d][0] * il0, O[mt][d][1] * il0);
            *(uint16_t*)&g_AO8[(size_t)(r0 + 8) * 256 + col] =
                pack2_e4m3(O[mt][d][2] * il1, O[mt][d][3] * il1);
        }
    }
}

// ---------------- fused tail: proj+residual, LN2, MLP, residual ----------------
// smem: sXM 4x(64x80)=20480, sH 20480, sB 3x(128x80)=30720  => 71680
#define XM8_OFF 0
#define H8_OFF  20480
#define B8_OFF  40960
#define SMEM_MLP8 71680

__device__ __forceinline__ void mlp_sub8(const uint8_t* __restrict__ Asm,
                                         const uint8_t* __restrict__ W, int half,
                                         uint8_t* sB, float acc[2][4][4], int tid) {
    int lane = tid & 31, warp = tid >> 5;
    int wm = warp & 1, wn = warp >> 1;
    int lrow = tid >> 1, lseg = (tid & 1) * 32;
    const uint8_t* bsrc0 = W + (size_t)(half * 128 + lrow) * 256 + lseg;
    uint32_t bd0 = smaddr(sB + (size_t)lrow * 80 + lseg);

    __syncthreads();
#define BPRE(st, kc)                                            \
    do {                                                        \
        uint32_t bd = bd0 + (st) * 10240;                       \
        const uint8_t* bs = bsrc0 + (size_t)(kc) * 64;          \
        cpasync16(bd, bs);                                      \
        cpasync16(bd + 16, bs + 16);                            \
        cpcommit();                                             \
    } while (0)
    BPRE(0, 0);
    BPRE(1, 1);
#pragma unroll
    for (int kc = 0; kc < 4; kc++) {
        if (kc < 3) asm volatile("cp.async.wait_group 1;\n");
        else        asm volatile("cp.async.wait_group 0;\n");
        __syncthreads();
        if (kc < 2) BPRE((kc + 2) % 3, kc + 2);
        const uint8_t* sBs = sB + (kc % 3) * 10240;
        const uint8_t* Ac = Asm + kc * 5120;
#pragma unroll
        for (int kk2 = 0; kk2 < 2; kk2++) {
            uint32_t af[2][4];
#pragma unroll
            for (int mt = 0; mt < 2; mt++)
                ldm4(af[mt], Ac + (size_t)(wm * 32 + mt * 16 + (lane & 15)) * 80 +
                             kk2 * 32 + ((lane >> 4) & 1) * 16);
            uint32_t bfr[2][4];
#pragma unroll
            for (int nb = 0; nb < 2; nb++)
                ldm4(bfr[nb], sBs + (size_t)(wn * 32 + nb * 16 + (lane & 15)) * 80 +
                              kk2 * 32 + ((lane >> 4) & 1) * 16);
#pragma unroll
            for (int mt = 0; mt < 2; mt++)
#pragma unroll
                for (int nt = 0; nt < 4; nt++)
                    mma16832(acc[mt][nt], af[mt],
                             bfr[nt >> 1][nt & 1], bfr[nt >> 1][(nt & 1) + 2]);
        }
    }
#undef BPRE
    __syncthreads();
}

__global__ void __launch_bounds__(256, 2) k_mlp(const float* __restrict__ bo,
                                                const float* __restrict__ gamA,
                                                const float* __restrict__ xres,
                                                const float* __restrict__ lng,
                                                const float* __restrict__ lnb,
                                                const float* __restrict__ gamv,
                                                float* __restrict__ outf) {
    extern __shared__ char dsm[];
    uint8_t* sXM = (uint8_t*)(dsm + XM8_OFF);
    uint8_t* sH  = (uint8_t*)(dsm + H8_OFF);
    uint8_t* sB  = (uint8_t*)(dsm + B8_OFF);
    int tid = threadIdx.x, lane = tid & 31, warp = tid >> 5;
    int gr0 = blockIdx.x * 64;
    int wm = warp & 1, wn = warp >> 1;
    int qr = lane >> 2, qc = (lane & 3) * 2;

    // ---- load AO8 rows into sH (chunk layout) ----
#pragma unroll
    for (int i = 0; i < 4; i++) {
        int linear = tid + i * 256;
        int row = linear >> 4;
        int off = (linear & 15) * 16;
        int ch = off >> 6, within = off & 63;
        *(uint4*)(sH + (size_t)ch * 5120 + (size_t)row * 80 + within) =
            *(const uint4*)(g_AO8 + (size_t)(gr0 + row) * 256 + off);
    }

    // ---- phase 0: out = x + gamA*(AO @ Wo^T + bo)  -> outf ----
#pragma unroll
    for (int half = 0; half < 2; half++) {
        float acc[2][4][4];
#pragma unroll
        for (int i = 0; i < 2; i++)
#pragma unroll
            for (int j = 0; j < 4; j++)
#pragma unroll
                for (int q = 0; q < 4; q++) acc[i][j][q] = 0.f;
        mlp_sub8(sH, g_W8o, half, sB, acc, tid);
#pragma unroll
        for (int mt = 0; mt < 2; mt++) {
            int gr = gr0 + wm * 32 + mt * 16 + qr;
#pragma unroll
            for (int nt = 0; nt < 4; nt++) {
                int col = half * 128 + wn * 32 + nt * 8 + qc;
                float b0 = bo[col], b1 = bo[col + 1];
                float gm0 = gamA[col], gm1 = gamA[col + 1];
                size_t i0 = (size_t)gr * 256 + col;
                size_t i1 = (size_t)(gr + 8) * 256 + col;
                float2 x0 = *(const float2*)(xres + i0);
                float2 x1 = *(const float2*)(xres + i1);
                float2 o0, o1;
                o0.x = x0.x + gm0 * (acc[mt][nt][0] + b0);
                o0.y = x0.y + gm1 * (acc[mt][nt][1] + b1);
                o1.x = x1.x + gm0 * (acc[mt][nt][2] + b0);
                o1.y = x1.y + gm1 * (acc[mt][nt][3] + b1);
                *(float2*)(outf + i0) = o0;
                *(float2*)(outf + i1) = o1;
            }
        }
    }
    __syncthreads();   // outf writes visible to all threads in CTA

    // ---- LN2 of outf rows (L1/L2-hot) -> sXM fp8 ----
    {
        float4 ga = ((const float4*)lng)[lane], gb = ((const float4*)lng)[lane + 32];
        float4 ba = ((const float4*)lnb)[lane], bb = ((const float4*)lnb)[lane + 32];
        int ch0 = lane >> 4;
        int off0 = (lane * 4) & 63;
#pragma unroll
        for (int i = 0; i < 8; i++) {
            int r = i * 8 + warp;
            const float4* rp = (const float4*)(outf + (size_t)(gr0 + r) * 256);
            float4 v0 = rp[lane], v1 = rp[lane + 32];
            float s  = v0.x + v0.y + v0.z + v0.w + v1.x + v1.y + v1.z + v1.w;
            float ss = v0.x * v0.x + v0.y * v0.y + v0.z * v0.z + v0.w * v0.w +
                       v1.x * v1.x + v1.y * v1.y + v1.z * v1.z + v1.w * v1.w;
#pragma unroll
            for (int o = 16; o > 0; o >>= 1) {
                s  += __shfl_xor_sync(0xffffffffu, s, o);
                ss += __shfl_xor_sync(0xffffffffu, ss, o);
            }
            float mean = s * (1.f / 256.f);
            float var  = ss * (1.f / 256.f) - mean * mean;
            float rst = rsqrtf(var + 1e-5f);
            *(uint32_t*)(sXM + (size_t)ch0 * 5120 + (size_t)r * 80 + off0) =
                pack4_e4m3((v0.x - mean) * rst * ga.x + ba.x,
                           (v0.y - mean) * rst * ga.y + ba.y,
                           (v0.z - mean) * rst * ga.z + ba.z,
                           (v0.w - mean) * rst * ga.w + ba.w);
            *(uint32_t*)(sXM + (size_t)(2 + ch0) * 5120 + (size_t)r * 80 + off0) =
                pack4_e4m3((v1.x - mean) * rst * gb.x + bb.x,
                           (v1.y - mean) * rst * gb.y + bb.y,
                           (v1.z - mean) * rst * gb.z + bb.z,
                           (v1.w - mean) * rst * gb.w + bb.w);
        }
    }

    // ---- phase A: H = silu(XM @ W1^T) -> sH fp8 ----
#pragma unroll
    for (int half = 0; half < 2; half++) {
        float acc[2][4][4];
#pragma unroll
        for (int i = 0; i < 2; i++)
#pragma unroll
            for (int j = 0; j < 4; j++)
#pragma unroll
                for (int q = 0; q < 4; q++) acc[i][j][q] = 0.f;
        mlp_sub8(sXM, g_W8_1, half, sB, acc, tid);
#pragma unroll
        for (int mt = 0; mt < 2; mt++) {
            int r0 = wm * 32 + mt * 16 + qr;
#pragma unroll
            for (int nt = 0; nt < 4; nt++) {
                int col = half * 128 + wn * 32 + nt * 8 + qc;
                int ch = col >> 6, off = col & 63;
                float c0 = acc[mt][nt][0], c1 = acc[mt][nt][1];
                float c2 = acc[mt][nt][2], c3 = acc[mt][nt][3];
                float s0 = c0 / (1.f + __expf(-c0));
                float s1 = c1 / (1.f + __expf(-c1));
                float s2 = c2 / (1.f + __expf(-c2));
                float s3 = c3 / (1.f + __expf(-c3));
                *(uint16_t*)(sH + (size_t)ch * 5120 + (size_t)r0 * 80 + off) = pack2_e4m3(s0, s1);
                *(uint16_t*)(sH + (size_t)ch * 5120 + (size_t)(r0 + 8) * 80 + off) = pack2_e4m3(s2, s3);
            }
        }
    }

    // ---- phase B: out += gamma_mlp * (H @ W2^T) ----
#pragma unroll
    for (int half = 0; half < 2; half++) {
        float acc[2][4][4];
#pragma unroll
        for (int i = 0; i < 2; i++)
#pragma unroll
            for (int j = 0; j < 4; j++)
#pragma unroll
                for (int q = 0; q < 4; q++) acc[i][j][q] = 0.f;
        mlp_sub8(sH, g_W8_2, half, sB, acc, tid);
#pragma unroll
        for (int mt = 0; mt < 2; mt++) {
            int gr = gr0 + wm * 32 + mt * 16 + qr;
#pragma unroll
            for (int nt = 0; nt < 4; nt++) {
                int col = half * 128 + wn * 32 + nt * 8 + qc;
                float gm0 = gamv[col], gm1 = gamv[col + 1];
                size_t i0 = (size_t)gr * 256 + col;
                size_t i1 = (size_t)(gr + 8) * 256 + col;
                float2 o0 = *(float2*)(outf + i0);
                float2 o1 = *(float2*)(outf + i1);
                o0.x += gm0 * acc[mt][nt][0];
                o0.y += gm1 * acc[mt][nt][1];
                o1.x += gm0 * acc[mt][nt][2];
                o1.y += gm1 * acc[mt][nt][3];
                *(float2*)(outf + i0) = o0;
                *(float2*)(outf + i1) = o1;
            }
        }
    }
}

// ---------------- launch ----------------
extern "C" void kernel_launch(void* const* d_in, const int* in_sizes, int n_in,
                              void* d_out, int out_size) {
    const float* x    = (const float*)d_in[0];
    const void*  mask = d_in[1];
    const float* pos  = (const float*)d_in[2];
    const float* Wemb = (const float*)d_in[3];
    const float* bemb = (const float*)d_in[4];
    const float* g1   = (const float*)d_in[5];
    const float* b1   = (const float*)d_in[6];
    const float* Wq   = (const float*)d_in[7];
    const float* bq   = (const float*)d_in[8];
    const float* Wk   = (const float*)d_in[9];
    const float* bk   = (const float*)d_in[10];
    const float* Wv   = (const float*)d_in[11];
    const float* bv   = (const float*)d_in[12];
    const float* Wo   = (const float*)d_in[13];
    const float* bo   = (const float*)d_in[14];
    const float* g2   = (const float*)d_in[15];
    const float* b2   = (const float*)d_in[16];
    const float* W1   = (const float*)d_in[17];
    const float* W2   = (const float*)d_in[18];
    const float* gam  = (const float*)d_in[19];
    const float* gmlp = (const float*)d_in[20];
    (void)in_sizes; (void)n_in;

    cudaFuncSetAttribute(k_gemm0, cudaFuncAttributeMaxDynamicSharedMemorySize, SMEM_G8);
    cudaFuncSetAttribute(k_mlp, cudaFuncAttributeMaxDynamicSharedMemorySize, SMEM_MLP8);

    float* outx = (float*)d_out;
    int write_mask = (out_size >= 16777216 + 65536) ? 1 : 0;
    float* outmask = outx + 16777216;

    k_prep<<<768, 256>>>(pos, Wemb, bemb, g1, b1, Wq, Wk, Wv, bq, bk, bv,
                         Wo, W1, W2, mask, outmask, write_mask);
    k_ln<<<8192, 256>>>(x);
    dim3 gq(6, 512);
    k_gemm0<<<gq, 256, SMEM_G8>>>();
    dim3 ga(256, 8);
    k_attn<<<ga, 256>>>();
    k_mlp<<<1024, 256, SMEM_MLP8>>>(bo, gam, x, g2, b2, gmlp, outx);
}

// round 14
// speedup vs baseline: 1.0118x; 1.0118x over previous
#include <cuda_runtime.h>
#include <cuda_bf16.h>
#include <stdint.h>

#define NTOK 65536
#define F 256

typedef __nv_bfloat16 bf16;
typedef __nv_bfloat162 bf162;

// ---------------- scratch ----------------
__device__ __align__(128) uint8_t g_XM8[(size_t)NTOK * F];       // fp8 LN1-mod output
__device__ __align__(128) uint8_t g_QK8[(size_t)NTOK * 512];     // fp8 Q|K per token
__device__ __align__(128) bf16 g_V[(size_t)NTOK * F];            // bf16 V
__device__ __align__(128) uint8_t g_AO8[(size_t)NTOK * F];       // fp8 attention output
__device__ __align__(128) float g_Ae[256 * F];
__device__ __align__(128) float g_Be[256 * F];
__device__ __align__(128) uint8_t g_W8qkv[768 * F];              // [n][k] e4m3
__device__ __align__(128) uint8_t g_W8o[F * F];
__device__ __align__(128) uint8_t g_W8_1[F * F];
__device__ __align__(128) uint8_t g_W8_2[F * F];
__device__ __align__(128) float g_bqkv[3 * F];
// Schraudolph-folded bias: valid -> 1064986823.0 ; masked -> 142239943.0
__device__ __align__(128) float g_bias[NTOK];

// ---------------- helpers ----------------
__device__ __forceinline__ uint32_t smaddr(const void* p) {
    return (uint32_t)__cvta_generic_to_shared(p);
}
__device__ __forceinline__ void cpasync16(uint32_t dst, const void* src) {
    asm volatile("cp.async.cg.shared.global [%0], [%1], 16;\n" :: "r"(dst), "l"(src));
}
__device__ __forceinline__ void cpcommit() {
    asm volatile("cp.async.commit_group;\n");
}
__device__ __forceinline__ void ldm2(uint32_t* r, const void* p) {
    asm volatile("ldmatrix.sync.aligned.m8n8.x2.shared.b16 {%0,%1}, [%2];\n"
                 : "=r"(r[0]), "=r"(r[1]) : "r"(smaddr(p)));
}
__device__ __forceinline__ void ldm4(uint32_t* r, const void* p) {
    asm volatile("ldmatrix.sync.aligned.m8n8.x4.shared.b16 {%0,%1,%2,%3}, [%4];\n"
                 : "=r"(r[0]), "=r"(r[1]), "=r"(r[2]), "=r"(r[3]) : "r"(smaddr(p)));
}
__device__ __forceinline__ void ldm4t(uint32_t* r, const void* p) {
    asm volatile("ldmatrix.sync.aligned.m8n8.x4.trans.shared.b16 {%0,%1,%2,%3}, [%4];\n"
                 : "=r"(r[0]), "=r"(r[1]), "=r"(r[2]), "=r"(r[3]) : "r"(smaddr(p)));
}
__device__ __forceinline__ void mma16816(float* d, const uint32_t* a, const uint32_t* b) {
    asm volatile("mma.sync.aligned.m16n8k16.row.col.f32.bf16.bf16.f32 "
                 "{%0,%1,%2,%3}, {%4,%5,%6,%7}, {%8,%9}, {%0,%1,%2,%3};\n"
                 : "+f"(d[0]), "+f"(d[1]), "+f"(d[2]), "+f"(d[3])
                 : "r"(a[0]), "r"(a[1]), "r"(a[2]), "r"(a[3]), "r"(b[0]), "r"(b[1]));
}
__device__ __forceinline__ void mma16832(float* d, const uint32_t* a, uint32_t b0, uint32_t b1) {
    asm volatile("mma.sync.aligned.m16n8k32.row.col.f32.e4m3.e4m3.f32 "
                 "{%0,%1,%2,%3}, {%4,%5,%6,%7}, {%8,%9}, {%0,%1,%2,%3};\n"
                 : "+f"(d[0]), "+f"(d[1]), "+f"(d[2]), "+f"(d[3])
                 : "r"(a[0]), "r"(a[1]), "r"(a[2]), "r"(a[3]), "r"(b0), "r"(b1));
}
__device__ __forceinline__ uint32_t packbf(float a, float b) {
    bf162 h = __floats2bfloat162_rn(a, b);
    return *reinterpret_cast<uint32_t*>(&h);
}
__device__ __forceinline__ uint16_t pack2_e4m3(float lo, float hi) {
    uint16_t r;
    asm("cvt.rn.satfinite.e4m3x2.f32 %0, %1, %2;" : "=h"(r) : "f"(hi), "f"(lo));
    return r;
}
__device__ __forceinline__ uint32_t pack4_e4m3(float v0, float v1, float v2, float v3) {
    uint16_t lo = pack2_e4m3(v0, v1);
    uint16_t hi = pack2_e4m3(v2, v3);
    return (uint32_t)lo | ((uint32_t)hi << 16);
}
__device__ __forceinline__ uint8_t to_e4m3(float a) {
    return (uint8_t)pack2_e4m3(a, 0.f);
}

// ---------------- fused prep ----------------
__global__ void k_prep(const float* __restrict__ pos, const float* __restrict__ Wemb,
                       const float* __restrict__ bemb, const float* __restrict__ g1,
                       const float* __restrict__ b1,
                       const float* __restrict__ Wq, const float* __restrict__ Wk,
                       const float* __restrict__ Wv, const float* __restrict__ bq,
                       const float* __restrict__ bk, const float* __restrict__ bv,
                       const float* __restrict__ Wo, const float* __restrict__ W1,
                       const float* __restrict__ W2,
                       const void* __restrict__ mask, float* __restrict__ outmask,
                       int write_out) {
    int blk = blockIdx.x;
    int tid = threadIdx.x;
    if (blk < 256) {
        __shared__ float p[F];
        int t = blk, c = tid;
        p[c] = pos[t * F + c];
        __syncthreads();
        float sh = bemb[c], sc = bemb[F + c];
#pragma unroll 4
        for (int k = 0; k < F; k++) {
            float pv = p[k];
            sh = fmaf(pv, Wemb[k * 512 + c], sh);
            sc = fmaf(pv, Wemb[k * 512 + 256 + c], sc);
        }
        g_Ae[t * F + c] = g1[c] * (1.f + sc);
        g_Be[t * F + c] = b1[c] * (1.f + sc) + sh;
    } else if (blk < 512) {
        int i = (blk - 256) * 256 + tid;
        int k = i >> 8, n = i & 255;
        g_W8qkv[(size_t)n * 256 + k]         = to_e4m3(Wq[i]);
        g_W8qkv[(size_t)(256 + n) * 256 + k] = to_e4m3(Wk[i]);
        g_W8qkv[(size_t)(512 + n) * 256 + k] = to_e4m3(Wv[i]);
        g_W8o[(size_t)n * 256 + k]  = to_e4m3(Wo[i]);
        g_W8_1[(size_t)n * 256 + k] = to_e4m3(W1[i]);
        g_W8_2[(size_t)n * 256 + k] = to_e4m3(W2[i]);
        if (i < F) {
            g_bqkv[i]         = bq[i];
            g_bqkv[F + i]     = bk[i];
            g_bqkv[2 * F + i] = bv[i];
        }
    } else {
        __shared__ int sAll[8];
        int w = blk - 512;
        uint32_t w0 = *(const uint32_t*)mask;
        int mode = (w0 == 0x01010101u) ? 0 : ((w0 == 0x3F800000u) ? 1 : 2);
        int idx = w * 256 + tid;
        int mv;
        if (mode == 0)      mv = (((const unsigned char*)mask)[idx] != 0);
        else if (mode == 1) mv = (((const float*)mask)[idx] != 0.f);
        else                mv = (((const int*)mask)[idx] != 0);
        g_bias[idx] = mv ? 1064986823.0f : 142239943.0f;
        unsigned bal = __ballot_sync(0xffffffffu, mv);
        if ((tid & 31) == 0) sAll[tid >> 5] = (bal == 0xffffffffu);
        __syncthreads();
        if (write_out) {
            int allv = sAll[0] & sAll[1] & sAll[2] & sAll[3] & sAll[4] & sAll[5] & sAll[6] & sAll[7];
            outmask[idx] = (mv && allv) ? 1.f : 0.f;
        }
    }
}

// ---------------- layernorm (LN1 + modulation) -> fp8 ----------------
__global__ void k_ln(const float* __restrict__ xin) {
    int warp = threadIdx.x >> 5, lane = threadIdx.x & 31;
    int tok = blockIdx.x * 8 + warp;
    const float4* row = (const float4*)(xin + (size_t)tok * F);
    float4 v0 = row[lane], v1 = row[lane + 32];
    float s  = v0.x + v0.y + v0.z + v0.w + v1.x + v1.y + v1.z + v1.w;
    float ss = v0.x * v0.x + v0.y * v0.y + v0.z * v0.z + v0.w * v0.w +
               v1.x * v1.x + v1.y * v1.y + v1.z * v1.z + v1.w * v1.w;
#pragma unroll
    for (int o = 16; o > 0; o >>= 1) {
        s  += __shfl_xor_sync(0xffffffffu, s, o);
        ss += __shfl_xor_sync(0xffffffffu, ss, o);
    }
    float mean = s * (1.f / 256.f);
    float var  = ss * (1.f / 256.f) - mean * mean;
    float r = rsqrtf(var + 1e-5f);
    const float4* a4 = (const float4*)(g_Ae + (size_t)(tok & 255) * F);
    const float4* b4 = (const float4*)(g_Be + (size_t)(tok & 255) * F);
    float4 a0 = a4[lane], a1 = a4[lane + 32];
    float4 b0 = b4[lane], b1 = b4[lane + 32];
    uint32_t* out = (uint32_t*)(g_XM8 + (size_t)tok * F);
    out[lane] = pack4_e4m3((v0.x - mean) * r * a0.x + b0.x,
                           (v0.y - mean) * r * a0.y + b0.y,
                           (v0.z - mean) * r * a0.z + b0.z,
                           (v0.w - mean) * r * a0.w + b0.w);
    out[lane + 32] = pack4_e4m3((v1.x - mean) * r * a1.x + b1.x,
                                (v1.y - mean) * r * a1.y + b1.y,
                                (v1.z - mean) * r * a1.z + b1.z,
                                (v1.w - mean) * r * a1.w + b1.w);
}

// ---------------- fp8 GEMM (QKV): C = XM8 @ Wqkv^T -> Q,K fp8 / V bf16 ----------------
#define SMEM_G8 61440

__global__ void __launch_bounds__(256, 2) k_gemm0() {
    extern __shared__ char dsm[];
    uint8_t* sA = (uint8_t*)dsm;
    uint8_t* sB = (uint8_t*)(dsm + 30720);

    int tid = threadIdx.x;
    int lane = tid & 31, warp = tid >> 5;
    int wm = warp & 1, wn = warp >> 1;
    int bm = blockIdx.y * 128, bn = blockIdx.x * 128;

    float acc[4][4][4];
#pragma unroll
    for (int i = 0; i < 4; i++)
#pragma unroll
        for (int j = 0; j < 4; j++)
#pragma unroll
            for (int q = 0; q < 4; q++) acc[i][j][q] = 0.f;

    int lrow = tid >> 1, lseg = (tid & 1) * 32;
    const uint8_t* asrc0 = g_XM8 + (size_t)(bm + lrow) * 256 + lseg;
    const uint8_t* bsrc0 = g_W8qkv + (size_t)(bn + lrow) * 256 + lseg;
    uint32_t ad0 = smaddr(sA + (size_t)lrow * 80 + lseg);
    uint32_t bd0 = smaddr(sB + (size_t)lrow * 80 + lseg);

#define PREFETCH(st, k0)                                        \
    do {                                                        \
        uint32_t ad = ad0 + (st) * 10240;                       \
        cpasync16(ad, asrc0 + (k0));                            \
        cpasync16(ad + 16, asrc0 + (k0) + 16);                  \
        uint32_t bd = bd0 + (st) * 10240;                       \
        cpasync16(bd, bsrc0 + (k0));                            \
        cpasync16(bd + 16, bsrc0 + (k0) + 16);                  \
        cpcommit();                                             \
    } while (0)

    PREFETCH(0, 0);
    PREFETCH(1, 64);
#pragma unroll
    for (int ks = 0; ks < 4; ks++) {
        if (ks < 3) asm volatile("cp.async.wait_group 1;\n");
        else        asm volatile("cp.async.wait_group 0;\n");
        __syncthreads();
        if (ks < 2) PREFETCH((ks + 2) % 3, (ks + 2) * 64);
        int st = ks % 3;
        const uint8_t* sAs = sA + st * 10240;
        const uint8_t* sBs = sB + st * 10240;
#pragma unroll
        for (int kk2 = 0; kk2 < 2; kk2++) {
            uint32_t af[4][4];
#pragma unroll
            for (int mt = 0; mt < 4; mt++)
                ldm4(af[mt], sAs + (size_t)(wm * 64 + mt * 16 + (lane & 15)) * 80 +
                             kk2 * 32 + ((lane >> 4) & 1) * 16);
            uint32_t bfr[2][4];
#pragma unroll
            for (int nb = 0; nb < 2; nb++)
                ldm4(bfr[nb], sBs + (size_t)(wn * 32 + nb * 16 + (lane & 15)) * 80 +
                              kk2 * 32 + ((lane >> 4) & 1) * 16);
#pragma unroll
            for (int mt = 0; mt < 4; mt++)
#pragma unroll
                for (int nt = 0; nt < 4; nt++)
                    mma16832(acc[mt][nt], af[mt],
                             bfr[nt >> 1][nt & 1], bfr[nt >> 1][(nt & 1) + 2]);
        }
    }
#undef PREFETCH

#pragma unroll
    for (int mt = 0; mt < 4; mt++) {
        int r0 = bm + wm * 64 + mt * 16 + (lane >> 2);
#pragma unroll
        for (int nt = 0; nt < 4; nt++) {
            int cb = bn + wn * 32 + nt * 8 + (lane & 3) * 2;
            float b0 = g_bqkv[cb], b1 = g_bqkv[cb + 1];
            float c0 = acc[mt][nt][0] + b0, c1 = acc[mt][nt][1] + b1;
            float c2 = acc[mt][nt][2] + b0, c3 = acc[mt][nt][3] + b1;
            if (cb < 512) {
                *(uint16_t*)&g_QK8[(size_t)r0 * 512 + cb]       = pack2_e4m3(c0, c1);
                *(uint16_t*)&g_QK8[(size_t)(r0 + 8) * 512 + cb] = pack2_e4m3(c2, c3);
            } else {
                int vc = cb - 512;
                *(bf162*)&g_V[(size_t)r0 * 256 + vc]       = __floats2bfloat162_rn(c0, c1);
                *(bf162*)&g_V[(size_t)(r0 + 8) * 256 + vc] = __floats2bfloat162_rn(c2, c3);
            }
        }
    }
}

// ---------------- attention: fp8 QK (m16n8k32), bf16 PV, Schraudolph softmax ----------------
__global__ void __launch_bounds__(256, 2) k_attn() {
    __shared__ uint8_t smK8[256][48];
    __shared__ bf16 smV[256][40];
    __shared__ float sB2[256];
    int w = blockIdx.x, h = blockIdx.y;
    int tid = threadIdx.x, warp = tid >> 5, lane = tid & 31;
    const uint8_t* kbase = g_QK8 + (size_t)(w * 256) * 512 + 256 + h * 32;
    const bf16* vbase = g_V + (size_t)(w * 256) * 256 + h * 32;

    {
        const uint4* ks = (const uint4*)(kbase + (size_t)tid * 512);
        uint4 k0 = ks[0], k1 = ks[1];
        const uint4* vs = (const uint4*)(vbase + (size_t)tid * 256);
        uint4 v0 = vs[0], v1 = vs[1], v2 = vs[2], v3 = vs[3];
        *(uint4*)&smK8[tid][0] = k0;
        *(uint4*)&smK8[tid][16] = k1;
        uint4* vd = (uint4*)&smV[tid][0];
        vd[0] = v0; vd[1] = v1; vd[2] = v2; vd[3] = v3;
        sB2[tid] = g_bias[w * 256 + tid];
    }

    const uint8_t* qbase = g_QK8 + (size_t)(w * 256) * 512 + h * 32;
    int qr = lane >> 2, qc = (lane & 3) * 2, qc4 = (lane & 3) * 4;
    uint32_t qf[2][4];
#pragma unroll
    for (int mt = 0; mt < 2; mt++) {
        const uint8_t* qp = qbase + (size_t)(warp * 32 + mt * 16) * 512;
        qf[mt][0] = *(const uint32_t*)(qp + (size_t)qr * 512 + qc4);
        qf[mt][1] = *(const uint32_t*)(qp + (size_t)(qr + 8) * 512 + qc4);
        qf[mt][2] = *(const uint32_t*)(qp + (size_t)qr * 512 + 16 + qc4);
        qf[mt][3] = *(const uint32_t*)(qp + (size_t)(qr + 8) * 512 + 16 + qc4);
    }
    __syncthreads();

    float O[2][4][4];
    float Osum[2][4];
#pragma unroll
    for (int mt = 0; mt < 2; mt++) {
#pragma unroll
        for (int q = 0; q < 4; q++) Osum[mt][q] = 0.f;
#pragma unroll
        for (int d = 0; d < 4; d++)
#pragma unroll
            for (int q = 0; q < 4; q++) O[mt][d][q] = 0.f;
    }
    const float K1 = 0.17677669529663687f * 1.4426950408889634f * 8388608.f;
    uint32_t onesb[2] = {0x3F803F80u, 0x3F803F80u};

#pragma unroll
    for (int c = 0; c < 8; c++) {
        uint32_t pa[2][4][2];
#pragma unroll
        for (int nt = 0; nt < 4; nt++) {
            int key0 = c * 32 + nt * 8;
            uint32_t kb[2];
            ldm2(kb, &smK8[key0 + (lane & 7)][((lane >> 3) & 1) * 16]);
            float s0[4] = {0.f, 0.f, 0.f, 0.f};
            float s1[4] = {0.f, 0.f, 0.f, 0.f};
            mma16832(s0, qf[0], kb[0], kb[1]);
            mma16832(s1, qf[1], kb[0], kb[1]);
            int kcol = key0 + qc;
            float b0 = sB2[kcol], b1 = sB2[kcol + 1];
            float p00 = __int_as_float((int)fmaf(s0[0], K1, b0));
            float p01 = __int_as_float((int)fmaf(s0[1], K1, b1));
            float p02 = __int_as_float((int)fmaf(s0[2], K1, b0));
            float p03 = __int_as_float((int)fmaf(s0[3], K1, b1));
            float p10 = __int_as_float((int)fmaf(s1[0], K1, b0));
            float p11 = __int_as_float((int)fmaf(s1[1], K1, b1));
            float p12 = __int_as_float((int)fmaf(s1[2], K1, b0));
            float p13 = __int_as_float((int)fmaf(s1[3], K1, b1));
            pa[0][nt][0] = packbf(p00, p01);
            pa[0][nt][1] = packbf(p02, p03);
            pa[1][nt][0] = packbf(p10, p11);
            pa[1][nt][1] = packbf(p12, p13);
        }
#pragma unroll
        for (int kt2 = 0; kt2 < 2; kt2++) {
            uint32_t af0[4] = {pa[0][2 * kt2][0], pa[0][2 * kt2][1],
                               pa[0][2 * kt2 + 1][0], pa[0][2 * kt2 + 1][1]};
            uint32_t af1[4] = {pa[1][2 * kt2][0], pa[1][2 * kt2][1],
                               pa[1][2 * kt2 + 1][0], pa[1][2 * kt2 + 1][1]};
            mma16816(Osum[0], af0, onesb);
            mma16816(Osum[1], af1, onesb);
#pragma unroll
            for (int d2 = 0; d2 < 2; d2++) {
                uint32_t vb4[4];
                ldm4t(vb4, &smV[c * 32 + kt2 * 16 + (lane & 15)][d2 * 16 + ((lane >> 4) & 1) * 8]);
                mma16816(O[0][2 * d2],     af0, vb4);
                mma16816(O[0][2 * d2 + 1], af0, vb4 + 2);
                mma16816(O[1][2 * d2],     af1, vb4);
                mma16816(O[1][2 * d2 + 1], af1, vb4 + 2);
            }
        }
    }

#pragma unroll
    for (int mt = 0; mt < 2; mt++) {
        float il0 = 1.f / Osum[mt][0];
        float il1 = 1.f / Osum[mt][2];
        int r0 = w * 256 + warp * 32 + mt * 16 + qr;
#pragma unroll
        for (int d = 0; d < 4; d++) {
            int col = h * 32 + d * 8 + qc;
            *(uint16_t*)&g_AO8[(size_t)r0 * 256 + col] =
                pack2_e4m3(O[mt][d][0] * il0, O[mt][d][1] * il0);
            *(uint16_t*)&g_AO8[(size_t)(r0 + 8) * 256 + col] =
                pack2_e4m3(O[mt][d][2] * il1, O[mt][d][3] * il1);
        }
    }
}

// ---------------- fp8 GEMM1: outx = x + gam*(AO8 @ Wo^T + bo) ----------------
__global__ void __launch_bounds__(256, 2) k_gemm1(const float* __restrict__ bias,
                                                  const float* __restrict__ xres,
                                                  const float* __restrict__ gamv,
                                                  float* __restrict__ outf) {
    extern __shared__ char dsm[];
    uint8_t* sA = (uint8_t*)dsm;
    uint8_t* sB = (uint8_t*)(dsm + 30720);

    int tid = threadIdx.x;
    int lane = tid & 31, warp = tid >> 5;
    int wm = warp & 1, wn = warp >> 1;
    int bm = blockIdx.y * 128, bn = blockIdx.x * 128;

    float acc[4][4][4];
#pragma unroll
    for (int i = 0; i < 4; i++)
#pragma unroll
        for (int j = 0; j < 4; j++)
#pragma unroll
            for (int q = 0; q < 4; q++) acc[i][j][q] = 0.f;

    int lrow = tid >> 1, lseg = (tid & 1) * 32;
    const uint8_t* asrc0 = g_AO8 + (size_t)(bm + lrow) * 256 + lseg;
    const uint8_t* bsrc0 = g_W8o + (size_t)(bn + lrow) * 256 + lseg;
    uint32_t ad0 = smaddr(sA + (size_t)lrow * 80 + lseg);
    uint32_t bd0 = smaddr(sB + (size_t)lrow * 80 + lseg);

#define PREFETCH(st, k0)                                        \
    do {                                                        \
        uint32_t ad = ad0 + (st) * 10240;                       \
        cpasync16(ad, asrc0 + (k0));                            \
        cpasync16(ad + 16, asrc0 + (k0) + 16);                  \
        uint32_t bd = bd0 + (st) * 10240;                       \
        cpasync16(bd, bsrc0 + (k0));                            \
        cpasync16(bd + 16, bsrc0 + (k0) + 16);                  \
        cpcommit();                                             \
    } while (0)

    PREFETCH(0, 0);
    PREFETCH(1, 64);
#pragma unroll
    for (int ks = 0; ks < 4; ks++) {
        if (ks < 3) asm volatile("cp.async.wait_group 1;\n");
        else        asm volatile("cp.async.wait_group 0;\n");
        __syncthreads();
        if (ks < 2) PREFETCH((ks + 2) % 3, (ks + 2) * 64);
        int st = ks % 3;
        const uint8_t* sAs = sA + st * 10240;
        const uint8_t* sBs = sB + st * 10240;
#pragma unroll
        for (int kk2 = 0; kk2 < 2; kk2++) {
            uint32_t af[4][4];
#pragma unroll
            for (int mt = 0; mt < 4; mt++)
                ldm4(af[mt], sAs + (size_t)(wm * 64 + mt * 16 + (lane & 15)) * 80 +
                             kk2 * 32 + ((lane >> 4) & 1) * 16);
            uint32_t bfr[2][4];
#pragma unroll
            for (int nb = 0; nb < 2; nb++)
                ldm4(bfr[nb], sBs + (size_t)(wn * 32 + nb * 16 + (lane & 15)) * 80 +
                              kk2 * 32 + ((lane >> 4) & 1) * 16);
#pragma unroll
            for (int mt = 0; mt < 4; mt++)
#pragma unroll
                for (int nt = 0; nt < 4; nt++)
                    mma16832(acc[mt][nt], af[mt],
                             bfr[nt >> 1][nt & 1], bfr[nt >> 1][(nt & 1) + 2]);
        }
    }
#undef PREFETCH

#pragma unroll
    for (int mt = 0; mt < 4; mt++) {
        int r0 = bm + wm * 64 + mt * 16 + (lane >> 2);
#pragma unroll
        for (int nt = 0; nt < 4; nt++) {
            int cb = bn + wn * 32 + nt * 8 + (lane & 3) * 2;
            float b0 = bias[cb], b1 = bias[cb + 1];
            float gm0 = gamv[cb], gm1 = gamv[cb + 1];
            size_t i0 = (size_t)r0 * 256 + cb, i1 = (size_t)(r0 + 8) * 256 + cb;
            float2 o0, o1;
            o0.x = xres[i0]     + gm0 * (acc[mt][nt][0] + b0);
            o0.y = xres[i0 + 1] + gm1 * (acc[mt][nt][1] + b1);
            o1.x = xres[i1]     + gm0 * (acc[mt][nt][2] + b0);
            o1.y = xres[i1 + 1] + gm1 * (acc[mt][nt][3] + b1);
            *(float2*)&outf[i0] = o0;
            *(float2*)&outf[i1] = o1;
        }
    }
}

// ---------------- fused MLP (fp8): LN2 + (XM@W1->silu) + (H@W2) + residual ----------------
#define XM8_OFF 0
#define H8_OFF  20480
#define B8_OFF  40960
#define SMEM_MLP8 71680

__device__ __forceinline__ void mlp_sub8(const uint8_t* __restrict__ Asm,
                                         const uint8_t* __restrict__ W, int half,
                                         uint8_t* sB, float acc[2][4][4], int tid) {
    int lane = tid & 31, warp = tid >> 5;
    int wm = warp & 1, wn = warp >> 1;
    int lrow = tid >> 1, lseg = (tid & 1) * 32;
    const uint8_t* bsrc0 = W + (size_t)(half * 128 + lrow) * 256 + lseg;
    uint32_t bd0 = smaddr(sB + (size_t)lrow * 80 + lseg);

    __syncthreads();
#define BPRE(st, kc)                                            \
    do {                                                        \
        uint32_t bd = bd0 + (st) * 10240;                       \
        const uint8_t* bs = bsrc0 + (size_t)(kc) * 64;          \
        cpasync16(bd, bs);                                      \
        cpasync16(bd + 16, bs + 16);                            \
        cpcommit();                                             \
    } while (0)
    BPRE(0, 0);
    BPRE(1, 1);
#pragma unroll
    for (int kc = 0; kc < 4; kc++) {
        if (kc < 3) asm volatile("cp.async.wait_group 1;\n");
        else        asm volatile("cp.async.wait_group 0;\n");
        __syncthreads();
        if (kc < 2) BPRE((kc + 2) % 3, kc + 2);
        const uint8_t* sBs = sB + (kc % 3) * 10240;
        const uint8_t* Ac = Asm + kc * 5120;
#pragma unroll
        for (int kk2 = 0; kk2 < 2; kk2++) {
            uint32_t af[2][4];
#pragma unroll
            for (int mt = 0; mt < 2; mt++)
                ldm4(af[mt], Ac + (size_t)(wm * 32 + mt * 16 + (lane & 15)) * 80 +
                             kk2 * 32 + ((lane >> 4) & 1) * 16);
            uint32_t bfr[2][4];
#pragma unroll
            for (int nb = 0; nb < 2; nb++)
                ldm4(bfr[nb], sBs + (size_t)(wn * 32 + nb * 16 + (lane & 15)) * 80 +
                              kk2 * 32 + ((lane >> 4) & 1) * 16);
#pragma unroll
            for (int mt = 0; mt < 2; mt++)
#pragma unroll
                for (int nt = 0; nt < 4; nt++)
                    mma16832(acc[mt][nt], af[mt],
                             bfr[nt >> 1][nt & 1], bfr[nt >> 1][(nt & 1) + 2]);
        }
    }
#undef BPRE
    __syncthreads();
}

__global__ void __launch_bounds__(256, 2) k_mlp(const float* __restrict__ lng,
                                                const float* __restrict__ lnb,
                                                const float* __restrict__ gamv,
                                                float* __restrict__ outf) {
    extern __shared__ char dsm[];
    uint8_t* sXM = (uint8_t*)(dsm + XM8_OFF);
    uint8_t* sH  = (uint8_t*)(dsm + H8_OFF);
    uint8_t* sB  = (uint8_t*)(dsm + B8_OFF);
    int tid = threadIdx.x, lane = tid & 31, warp = tid >> 5;
    int gr0 = blockIdx.x * 64;

    {
        float4 ga = ((const float4*)lng)[lane], gb = ((const float4*)lng)[lane + 32];
        float4 ba = ((const float4*)lnb)[lane], bb = ((const float4*)lnb)[lane + 32];
        int ch0 = lane >> 4;
        int off0 = (lane * 4) & 63;
#pragma unroll
        for (int i = 0; i < 8; i++) {
            int r = i * 8 + warp;
            const float4* rp = (const float4*)(outf + (size_t)(gr0 + r) * 256);
            float4 v0 = rp[lane], v1 = rp[lane + 32];
            float s  = v0.x + v0.y + v0.z + v0.w + v1.x + v1.y + v1.z + v1.w;
            float ss = v0.x * v0.x + v0.y * v0.y + v0.z * v0.z + v0.w * v0.w +
                       v1.x * v1.x + v1.y * v1.y + v1.z * v1.z + v1.w * v1.w;
#pragma unroll
            for (int o = 16; o > 0; o >>= 1) {
                s  += __shfl_xor_sync(0xffffffffu, s, o);
                ss += __shfl_xor_sync(0xffffffffu, ss, o);
            }
            float mean = s * (1.f / 256.f);
            float var  = ss * (1.f / 256.f) - mean * mean;
            float rst = rsqrtf(var + 1e-5f);
            *(uint32_t*)(sXM + (size_t)ch0 * 5120 + (size_t)r * 80 + off0) =
                pack4_e4m3((v0.x - mean) * rst * ga.x + ba.x,
                           (v0.y - mean) * rst * ga.y + ba.y,
                           (v0.z - mean) * rst * ga.z + ba.z,
                           (v0.w - mean) * rst * ga.w + ba.w);
            *(uint32_t*)(sXM + (size_t)(2 + ch0) * 5120 + (size_t)r * 80 + off0) =
                pack4_e4m3((v1.x - mean) * rst * gb.x + bb.x,
                           (v1.y - mean) * rst * gb.y + bb.y,
                           (v1.z - mean) * rst * gb.z + bb.z,
                           (v1.w - mean) * rst * gb.w + bb.w);
        }
    }

    int wm = warp & 1, wn = warp >> 1;
    int qr = lane >> 2, qc = (lane & 3) * 2;

#pragma unroll
    for (int half = 0; half < 2; half++) {
        float acc[2][4][4];
#pragma unroll
        for (int i = 0; i < 2; i++)
#pragma unroll
            for (int j = 0; j < 4; j++)
#pragma unroll
                for (int q = 0; q < 4; q++) acc[i][j][q] = 0.f;
        mlp_sub8(sXM, g_W8_1, half, sB, acc, tid);
#pragma unroll
        for (int mt = 0; mt < 2; mt++) {
            int r0 = wm * 32 + mt * 16 + qr;
#pragma unroll
            for (int nt = 0; nt < 4; nt++) {
                int col = half * 128 + wn * 32 + nt * 8 + qc;
                int ch = col >> 6, off = col & 63;
                float c0 = acc[mt][nt][0], c1 = acc[mt][nt][1];
                float c2 = acc[mt][nt][2], c3 = acc[mt][nt][3];
                float s0 = c0 / (1.f + __expf(-c0));
                float s1 = c1 / (1.f + __expf(-c1));
                float s2 = c2 / (1.f + __expf(-c2));
                float s3 = c3 / (1.f + __expf(-c3));
                *(uint16_t*)(sH + (size_t)ch * 5120 + (size_t)r0 * 80 + off) = pack2_e4m3(s0, s1);
                *(uint16_t*)(sH + (size_t)ch * 5120 + (size_t)(r0 + 8) * 80 + off) = pack2_e4m3(s2, s3);
            }
        }
    }

#pragma unroll
    for (int half = 0; half < 2; half++) {
        float acc[2][4][4];
#pragma unroll
        for (int i = 0; i < 2; i++)
#pragma unroll
            for (int j = 0; j < 4; j++)
#pragma unroll
                for (int q = 0; q < 4; q++) acc[i][j][q] = 0.f;
        mlp_sub8(sH, g_W8_2, half, sB, acc, tid);
#pragma unroll
        for (int mt = 0; mt < 2; mt++) {
            int gr = gr0 + wm * 32 + mt * 16 + qr;
#pragma unroll
            for (int nt = 0; nt < 4; nt++) {
                int col = half * 128 + wn * 32 + nt * 8 + qc;
                float gm0 = gamv[col], gm1 = gamv[col + 1];
                size_t i0 = (size_t)gr * 256 + col;
                size_t i1 = (size_t)(gr + 8) * 256 + col;
                float2 o0 = *(float2*)(outf + i0);
                float2 o1 = *(float2*)(outf + i1);
                o0.x += gm0 * acc[mt][nt][0];
                o0.y += gm1 * acc[mt][nt][1];
                o1.x += gm0 * acc[mt][nt][2];
                o1.y += gm1 * acc[mt][nt][3];
                *(float2*)(outf + i0) = o0;
                *(float2*)(outf + i1) = o1;
            }
        }
    }
}

// ---------------- launch ----------------
extern "C" void kernel_launch(void* const* d_in, const int* in_sizes, int n_in,
                              void* d_out, int out_size) {
    const float* x    = (const float*)d_in[0];
    const void*  mask = d_in[1];
    const float* pos  = (const float*)d_in[2];
    const float* Wemb = (const float*)d_in[3];
    const float* bemb = (const float*)d_in[4];
    const float* g1   = (const float*)d_in[5];
    const float* b1   = (const float*)d_in[6];
    const float* Wq   = (const float*)d_in[7];
    const float* bq   = (const float*)d_in[8];
    const float* Wk   = (const float*)d_in[9];
    const float* bk   = (const float*)d_in[10];
    const float* Wv   = (const float*)d_in[11];
    const float* bv   = (const float*)d_in[12];
    const float* Wo   = (const float*)d_in[13];
    const float* bo   = (const float*)d_in[14];
    const float* g2   = (const float*)d_in[15];
    const float* b2   = (const float*)d_in[16];
    const float* W1   = (const float*)d_in[17];
    const float* W2   = (const float*)d_in[18];
    const float* gam  = (const float*)d_in[19];
    const float* gmlp = (const float*)d_in[20];
    (void)in_sizes; (void)n_in;

    cudaFuncSetAttribute(k_gemm0, cudaFuncAttributeMaxDynamicSharedMemorySize, SMEM_G8);
    cudaFuncSetAttribute(k_gemm1, cudaFuncAttributeMaxDynamicSharedMemorySize, SMEM_G8);
    cudaFuncSetAttribute(k_mlp, cudaFuncAttributeMaxDynamicSharedMemorySize, SMEM_MLP8);

    float* outx = (float*)d_out;
    int write_mask = (out_size >= 16777216 + 65536) ? 1 : 0;
    float* outmask = outx + 16777216;

    k_prep<<<768, 256>>>(pos, Wemb, bemb, g1, b1, Wq, Wk, Wv, bq, bk, bv,
                         Wo, W1, W2, mask, outmask, write_mask);
    k_ln<<<8192, 256>>>(x);
    dim3 gq(6, 512);
    k_gemm0<<<gq, 256, SMEM_G8>>>();
    dim3 ga(256, 8);
    k_attn<<<ga, 256>>>();
    dim3 g2d(2, 512);
    k_gemm1<<<g2d, 256, SMEM_G8>>>(bo, x, gam, outx);
    k_mlp<<<1024, 256, SMEM_MLP8>>>(g2, b2, gmlp, outx);
}